// round 3
// baseline (speedup 1.0000x reference)
#include <cuda_runtime.h>
#include <stdint.h>

#define NB 32768
#define NE 1024

static __device__ __forceinline__ uint32_t rotl32(uint32_t x, int r) {
    return __funnelshift_l(x, x, r);
}

// threefry2x32 with key (0, 42), input block (x0=0, x1=i).
// Returns XOR of both output words — matches jax
// _threefry_random_bits_partitionable for bit_width=32 (bits1 ^ bits2),
// with counts_hi = 0, counts_lo = flat index (size < 2^32).
static __device__ __forceinline__ uint32_t threefry_xor(uint32_t i) {
    const uint32_t KS0 = 0u;
    const uint32_t KS1 = 42u;
    const uint32_t KS2 = 0x1BD11BDAu ^ KS0 ^ KS1;

    uint32_t x0 = KS0;        // counts_hi (=0) + ks0
    uint32_t x1 = i + KS1;    // counts_lo + ks1

    // rounds 1-4: rotations {13,15,26,6}
    x0 += x1; x1 = rotl32(x1, 13); x1 ^= x0;
    x0 += x1; x1 = rotl32(x1, 15); x1 ^= x0;
    x0 += x1; x1 = rotl32(x1, 26); x1 ^= x0;
    x0 += x1; x1 = rotl32(x1,  6); x1 ^= x0;
    x0 += KS1; x1 += KS2 + 1u;
    // rounds 5-8: {17,29,16,24}
    x0 += x1; x1 = rotl32(x1, 17); x1 ^= x0;
    x0 += x1; x1 = rotl32(x1, 29); x1 ^= x0;
    x0 += x1; x1 = rotl32(x1, 16); x1 ^= x0;
    x0 += x1; x1 = rotl32(x1, 24); x1 ^= x0;
    x0 += KS2; x1 += KS0 + 2u;
    // rounds 9-12: {13,15,26,6}
    x0 += x1; x1 = rotl32(x1, 13); x1 ^= x0;
    x0 += x1; x1 = rotl32(x1, 15); x1 ^= x0;
    x0 += x1; x1 = rotl32(x1, 26); x1 ^= x0;
    x0 += x1; x1 = rotl32(x1,  6); x1 ^= x0;
    x0 += KS0; x1 += KS1 + 3u;
    // rounds 13-16: {17,29,16,24}
    x0 += x1; x1 = rotl32(x1, 17); x1 ^= x0;
    x0 += x1; x1 = rotl32(x1, 29); x1 ^= x0;
    x0 += x1; x1 = rotl32(x1, 16); x1 ^= x0;
    x0 += x1; x1 = rotl32(x1, 24); x1 ^= x0;
    x0 += KS1; x1 += KS2 + 4u;
    // rounds 17-20: {13,15,26,6}
    x0 += x1; x1 = rotl32(x1, 13); x1 ^= x0;
    x0 += x1; x1 = rotl32(x1, 15); x1 ^= x0;
    x0 += x1; x1 = rotl32(x1, 26); x1 ^= x0;
    x0 += x1; x1 = rotl32(x1,  6); x1 ^= x0;
    x0 += KS2; x1 += KS0 + 5u;

    return x0 ^ x1;   // jax 32-bit partitionable combine
}

__global__ __launch_bounds__(256)
void dnm_kernel(const float* __restrict__ embeds,
                const float* __restrict__ factors,
                const float* __restrict__ mask_token,
                float* __restrict__ out_embeds,
                float* __restrict__ out_mask) {
    __shared__ uint32_t sm_m[NE];       // 23-bit score mantissas, monotone in score
    __shared__ uint32_t sh_hist[256];
    __shared__ uint16_t sh_cand[NE];
    __shared__ int sh_cnt;
    __shared__ int sh_k;
    __shared__ int sh_bucket;
    __shared__ int sh_rem;
    __shared__ uint32_t sh_thrM;
    __shared__ int sh_thrC;

    const int row = blockIdx.x;
    const int tid = threadIdx.x;

    // ---- Phase 1: RNG -> mantissas in smem ------------------------------
    #pragma unroll
    for (int t = 0; t < 4; t++) {
        const int col = tid + t * 256;
        const uint32_t flat = (uint32_t)(row * NE + col);  // < 2^25
        const uint32_t bits = threefry_xor(flat);
        sm_m[col] = bits >> 9;
    }
    sh_hist[tid] = 0u;
    if (tid == 0) {
        sh_cnt = 0;
        const float f = __ldg(&factors[row]);
        int k = (int)floorf(307.2f * f);   // f32(1024*0.3) * factor, floor
        if (k < 1) k = 1;
        sh_k = k;
    }
    __syncthreads();

    // ---- Phase 2: histogram on top 8 of 23 mantissa bits ----------------
    #pragma unroll
    for (int t = 0; t < 4; t++) {
        const int col = tid + t * 256;
        atomicAdd(&sh_hist[sm_m[col] >> 15], 1u);
    }
    __syncthreads();

    // ---- Phase 3: warp 0 scans 256 bins, finds bucket of k-th smallest --
    if (tid < 32) {
        const int lane = tid;
        uint32_t v[8];
        uint32_t s = 0;
        #pragma unroll
        for (int t = 0; t < 8; t++) { v[t] = sh_hist[lane * 8 + t]; s += v[t]; }
        // inclusive scan of per-lane sums
        uint32_t incl = s;
        #pragma unroll
        for (int o = 1; o < 32; o <<= 1) {
            uint32_t n = __shfl_up_sync(0xFFFFFFFFu, incl, o);
            if (lane >= o) incl += n;
        }
        const uint32_t excl = incl - s;
        const uint32_t k = (uint32_t)sh_k;
        if (excl < k && k <= incl) {     // unique lane
            uint32_t c = excl;
            #pragma unroll
            for (int t = 0; t < 8; t++) {
                if (k <= c + v[t]) { sh_bucket = lane * 8 + t; sh_rem = (int)(k - c); break; }
                c += v[t];
            }
        }
    }
    __syncthreads();

    // ---- Phase 4: collect candidates in the boundary bucket -------------
    const uint32_t bkt = (uint32_t)sh_bucket;
    #pragma unroll
    for (int t = 0; t < 4; t++) {
        const int col = tid + t * 256;
        if ((sm_m[col] >> 15) == bkt) {
            const int p = atomicAdd(&sh_cnt, 1);
            sh_cand[p] = (uint16_t)col;
        }
    }
    __syncthreads();

    // ---- Phase 5: warp 0 resolves exact threshold key (M*, c*) ----------
    if (tid < 32) {
        const int c = sh_cnt;
        const int rem = sh_rem;
        for (int idx = tid; idx < c; idx += 32) {
            const int ci = sh_cand[idx];
            const uint32_t mi = sm_m[ci];
            int rank = 0;
            for (int j = 0; j < c; j++) {
                const int cj = sh_cand[j];
                const uint32_t mj = sm_m[cj];
                rank += (mj < mi) || (mj == mi && cj < ci);
            }
            if (rank == rem - 1) { sh_thrM = mi; sh_thrC = ci; }
        }
    }
    __syncthreads();

    // ---- Phase 6: apply mask, vectorized f32x4 --------------------------
    const uint32_t thrM = sh_thrM;
    const int thrC = sh_thrC;
    const float4* emb4 = (const float4*)(embeds) + (size_t)row * (NE / 4);
    const float4* mt4 = (const float4*)(mask_token);
    float4* oe4 = (float4*)(out_embeds) + (size_t)row * (NE / 4);
    float4* om4 = (float4*)(out_mask) + (size_t)row * (NE / 4);

    const uint4 mv = ((const uint4*)sm_m)[tid];     // 4 consecutive mantissas
    const float4 e = emb4[tid];
    const float4 mt = __ldg(&mt4[tid]);
    const int cbase = tid * 4;

    // masked  <=>  (m, col) <= (M*, c*) lexicographically
    const bool k0 = (mv.x < thrM) || (mv.x == thrM && (cbase + 0) <= thrC);
    const bool k1 = (mv.y < thrM) || (mv.y == thrM && (cbase + 1) <= thrC);
    const bool k2 = (mv.z < thrM) || (mv.z == thrM && (cbase + 2) <= thrC);
    const bool k3 = (mv.w < thrM) || (mv.w == thrM && (cbase + 3) <= thrC);

    float4 oe, om;
    oe.x = k0 ? mt.x : e.x;  om.x = k0 ? 0.0f : 1.0f;
    oe.y = k1 ? mt.y : e.y;  om.y = k1 ? 0.0f : 1.0f;
    oe.z = k2 ? mt.z : e.z;  om.z = k2 ? 0.0f : 1.0f;
    oe.w = k3 ? mt.w : e.w;  om.w = k3 ? 0.0f : 1.0f;

    oe4[tid] = oe;
    om4[tid] = om;
}

extern "C" void kernel_launch(void* const* d_in, const int* in_sizes, int n_in,
                              void* d_out, int out_size) {
    const float* embeds = (const float*)d_in[0];       // [32768, 1024] f32
    const float* factors = (const float*)d_in[1];      // [32768] f32
    const float* mask_token = (const float*)d_in[2];   // [1, 1024] f32

    float* out_embeds = (float*)d_out;                 // [B, E]
    float* out_mask = out_embeds + (size_t)NB * NE;    // [B, E]

    dnm_kernel<<<NB, 256>>>(embeds, factors, mask_token, out_embeds, out_mask);
}

// round 4
// speedup vs baseline: 1.0638x; 1.0638x over previous
#include <cuda_runtime.h>
#include <stdint.h>

#define NB 32768
#define NE 1024

static __device__ __forceinline__ uint32_t rotl32(uint32_t x, int r) {
    return __funnelshift_l(x, x, r);
}

// Force an integer add onto the FMA pipe: d = a*one + b, where `one` is an
// opaque runtime value (==1). ptxas emits IMAD (fma pipe) instead of IADD3
// (alu pipe), relieving the binding alu pipe.
static __device__ __forceinline__ uint32_t fadd(uint32_t a, uint32_t b, uint32_t one) {
    uint32_t d;
    asm("mad.lo.u32 %0, %1, %2, %3;" : "=r"(d) : "r"(a), "r"(one), "r"(b));
    return d;
}
#define FADDC(d, a, C) asm("mad.lo.u32 %0, %1, %2, %3;" : "=r"(d) : "r"(a), "r"(one), "n"(C))

// threefry2x32, key (0,42), block (0, i). Returns x0^x1 after 20 rounds —
// matches jax _threefry_random_bits_partitionable (bit_width=32).
// Caller passes i with +42 (ks1) pre-added.
static __device__ __forceinline__ uint32_t threefry_xor(uint32_t x1, uint32_t one) {
    const uint32_t KS2 = 0x1BD11BDAu ^ 42u;
    uint32_t x0;
    // round 1: x0 starts at ks0=0 -> x0 = x1
    x0 = x1;                    x1 = rotl32(x1, 13) ^ x0;
    x0 = fadd(x0, x1, one);     x1 = rotl32(x1, 15) ^ x0;
    x0 = fadd(x0, x1, one);     x1 = rotl32(x1, 26) ^ x0;
    x0 = fadd(x0, x1, one);     x1 = rotl32(x1,  6) ^ x0;
    FADDC(x0, x0, 42u);  FADDC(x1, x1, (0x1BD11BDAu ^ 42u) + 1u);
    x0 = fadd(x0, x1, one);     x1 = rotl32(x1, 17) ^ x0;
    x0 = fadd(x0, x1, one);     x1 = rotl32(x1, 29) ^ x0;
    x0 = fadd(x0, x1, one);     x1 = rotl32(x1, 16) ^ x0;
    x0 = fadd(x0, x1, one);     x1 = rotl32(x1, 24) ^ x0;
    FADDC(x0, x0, (0x1BD11BDAu ^ 42u));  FADDC(x1, x1, 2u);
    x0 = fadd(x0, x1, one);     x1 = rotl32(x1, 13) ^ x0;
    x0 = fadd(x0, x1, one);     x1 = rotl32(x1, 15) ^ x0;
    x0 = fadd(x0, x1, one);     x1 = rotl32(x1, 26) ^ x0;
    x0 = fadd(x0, x1, one);     x1 = rotl32(x1,  6) ^ x0;
    /* x0 += ks0 (=0): skip */           FADDC(x1, x1, 45u);
    x0 = fadd(x0, x1, one);     x1 = rotl32(x1, 17) ^ x0;
    x0 = fadd(x0, x1, one);     x1 = rotl32(x1, 29) ^ x0;
    x0 = fadd(x0, x1, one);     x1 = rotl32(x1, 16) ^ x0;
    x0 = fadd(x0, x1, one);     x1 = rotl32(x1, 24) ^ x0;
    FADDC(x0, x0, 42u);  FADDC(x1, x1, (0x1BD11BDAu ^ 42u) + 4u);
    x0 = fadd(x0, x1, one);     x1 = rotl32(x1, 13) ^ x0;
    x0 = fadd(x0, x1, one);     x1 = rotl32(x1, 15) ^ x0;
    x0 = fadd(x0, x1, one);     x1 = rotl32(x1, 26) ^ x0;
    x0 = fadd(x0, x1, one);     x1 = rotl32(x1,  6) ^ x0;
    FADDC(x0, x0, (0x1BD11BDAu ^ 42u));  FADDC(x1, x1, 5u);
    (void)KS2;
    return x0 ^ x1;
}

__global__ __launch_bounds__(256)
void dnm_kernel(const float4* __restrict__ embeds,
                const float* __restrict__ factors,
                const float4* __restrict__ mask_token,
                float4* __restrict__ out_embeds,
                float4* __restrict__ out_mask,
                uint32_t one) {
    __shared__ uint32_t sh_hist[256];
    __shared__ unsigned long long sh_cand[1040];   // unique keys (m<<10)|col
    __shared__ int sh_cnt;
    __shared__ int sh_k;
    __shared__ int sh_bucket;
    __shared__ int sh_rem;
    __shared__ unsigned long long sh_thr;

    const int row = blockIdx.x;
    const int tid = threadIdx.x;

    // Prefetch the streaming data early; threefry compute hides the latency.
    const float4 e  = embeds[(size_t)row * (NE / 4) + tid];
    const float4 mt = __ldg(&mask_token[tid]);

    sh_hist[tid] = 0u;
    if (tid == 0) {
        sh_cnt = 0;
        const float f = __ldg(&factors[row]);
        int k = (int)floorf(307.2f * f);   // f32(1024*0.3)*factor, floor
        sh_k = k < 1 ? 1 : k;
    }
    __syncthreads();

    // ---- Phase 1: RNG for 4 CONTIGUOUS columns per thread + fused hist ---
    uint32_t m[4];
    const uint32_t base = (uint32_t)(row * NE + tid * 4) + 42u;  // +ks1 baked in
    #pragma unroll
    for (int j = 0; j < 4; j++) {
        const uint32_t bits = threefry_xor(base + j, one);
        m[j] = bits >> 9;                       // 23-bit score mantissa
        atomicAdd(&sh_hist[bits >> 24], 1u);    // bucket = top 8 bits
    }
    __syncthreads();

    // ---- Phase 2: warp 0 scans 256 bins for the k-th-smallest bucket -----
    if (tid < 32) {
        const int lane = tid;
        uint32_t v[8];
        uint32_t s = 0;
        #pragma unroll
        for (int t = 0; t < 8; t++) { v[t] = sh_hist[lane * 8 + t]; s += v[t]; }
        uint32_t incl = s;
        #pragma unroll
        for (int o = 1; o < 32; o <<= 1) {
            uint32_t n = __shfl_up_sync(0xFFFFFFFFu, incl, o);
            if (lane >= o) incl += n;
        }
        const uint32_t excl = incl - s;
        const uint32_t k = (uint32_t)sh_k;
        if (excl < k && k <= incl) {            // unique lane
            uint32_t c = excl;
            #pragma unroll
            for (int t = 0; t < 8; t++) {
                if (k <= c + v[t]) { sh_bucket = lane * 8 + t; sh_rem = (int)(k - c); break; }
                c += v[t];
            }
        }
    }
    __syncthreads();

    // ---- Phase 3: collect boundary-bucket candidates as unique keys ------
    const uint32_t bkt = (uint32_t)sh_bucket;
    #pragma unroll
    for (int j = 0; j < 4; j++) {
        if ((m[j] >> 15) == bkt) {
            const int p = atomicAdd(&sh_cnt, 1);
            sh_cand[p] = ((unsigned long long)m[j] << 10) | (unsigned)(tid * 4 + j);
        }
    }
    __syncthreads();

    // ---- Phase 4: warp 0 finds the exact k-th smallest key ---------------
    if (tid < 32) {
        const int c = sh_cnt;
        const int rem = sh_rem;
        for (int idx = tid; idx < c; idx += 32) {
            const unsigned long long key = sh_cand[idx];
            int rank = 0;
            for (int j2 = 0; j2 < c; j2++) rank += (sh_cand[j2] < key);
            if (rank == rem - 1) sh_thr = key;   // keys unique -> one writer
        }
    }
    __syncthreads();

    // ---- Phase 5: apply mask (masked <=> key <= thr), vectorized ---------
    const unsigned long long thr = sh_thr;
    const unsigned cbase = (unsigned)(tid * 4);

    const bool k0 = ((((unsigned long long)m[0] << 10) | (cbase + 0)) <= thr);
    const bool k1 = ((((unsigned long long)m[1] << 10) | (cbase + 1)) <= thr);
    const bool k2 = ((((unsigned long long)m[2] << 10) | (cbase + 2)) <= thr);
    const bool k3 = ((((unsigned long long)m[3] << 10) | (cbase + 3)) <= thr);

    float4 oe, om;
    oe.x = k0 ? mt.x : e.x;  om.x = k0 ? 0.0f : 1.0f;
    oe.y = k1 ? mt.y : e.y;  om.y = k1 ? 0.0f : 1.0f;
    oe.z = k2 ? mt.z : e.z;  om.z = k2 ? 0.0f : 1.0f;
    oe.w = k3 ? mt.w : e.w;  om.w = k3 ? 0.0f : 1.0f;

    out_embeds[(size_t)row * (NE / 4) + tid] = oe;
    out_mask[(size_t)row * (NE / 4) + tid]   = om;
}

extern "C" void kernel_launch(void* const* d_in, const int* in_sizes, int n_in,
                              void* d_out, int out_size) {
    const float4* embeds = (const float4*)d_in[0];     // [32768, 1024] f32
    const float* factors = (const float*)d_in[1];      // [32768] f32
    const float4* mask_token = (const float4*)d_in[2]; // [1, 1024] f32

    float* out = (float*)d_out;
    float4* out_embeds = (float4*)out;                       // [B, E]
    float4* out_mask = (float4*)(out + (size_t)NB * NE);     // [B, E]

    dnm_kernel<<<NB, 256>>>(embeds, factors, mask_token, out_embeds, out_mask, 1u);
}